// round 9
// baseline (speedup 1.0000x reference)
#include <cuda_runtime.h>
#include <cuda_fp16.h>
#include <math.h>
#include <stdint.h>

#define B_  32
#define CI_ 128
#define CO_ 256
#define H_  64
#define W_  64
#define E_  8
#define HW_ 4096
#define XROWS 66
#define XPLANE (XROWS * 64)   // 4224 halves per (kw,b,ci)

// ---------------- scratch ----------------
__device__ float g_pooled[B_ * CI_];
__device__ float g_rw[B_ * E_];
__device__ __half g_x3[(size_t)3 * B_ * CI_ * XPLANE];      // kw-shifted, halo-padded x (fp16)
__device__ __half g_wh[(size_t)B_ * 9 * CO_ * CI_];         // [b][r][co][ci]
__device__ float g_S[(size_t)B_ * 9 * CI_];                 // window sums of x per (b,r,ci)
__device__ float g_ca[B_ * CO_];

// ---------------- PTX helpers (base sm_103 PTX only) ----------------
__device__ __forceinline__ uint32_t smem_u32(const void* p) {
    uint32_t a;
    asm("{ .reg .u64 t; cvta.to.shared.u64 t, %1; cvt.u32.u64 %0, t; }" : "=r"(a) : "l"(p));
    return a;
}
__device__ __forceinline__ void ldsm4(uint32_t* r, uint32_t addr) {
    asm volatile("ldmatrix.sync.aligned.m8n8.x4.shared.b16 {%0,%1,%2,%3}, [%4];"
                 : "=r"(r[0]), "=r"(r[1]), "=r"(r[2]), "=r"(r[3]) : "r"(addr));
}
__device__ __forceinline__ void ldsm4t(uint32_t* r, uint32_t addr) {
    asm volatile("ldmatrix.sync.aligned.m8n8.x4.trans.shared.b16 {%0,%1,%2,%3}, [%4];"
                 : "=r"(r[0]), "=r"(r[1]), "=r"(r[2]), "=r"(r[3]) : "r"(addr));
}
__device__ __forceinline__ void mma_f16(float* d, const uint32_t* a, const uint32_t* b) {
    asm volatile(
        "mma.sync.aligned.m16n8k16.row.col.f32.f16.f16.f32 "
        "{%0,%1,%2,%3}, {%4,%5,%6,%7}, {%8,%9}, {%0,%1,%2,%3};"
        : "+f"(d[0]), "+f"(d[1]), "+f"(d[2]), "+f"(d[3])
        : "r"(a[0]), "r"(a[1]), "r"(a[2]), "r"(a[3]), "r"(b[0]), "r"(b[1]));
}
__device__ __forceinline__ void cp16(uint32_t dst, const void* src) {
    asm volatile("cp.async.cg.shared.global [%0], [%1], 16;" :: "r"(dst), "l"(src) : "memory");
}
#define CP_COMMIT() asm volatile("cp.async.commit_group;" ::: "memory")
#define CP_WAIT1()  asm volatile("cp.async.wait_group 1;" ::: "memory")

// ---------------- K1: x -> fp16 shifted copies + pooled mean + window sums ---
__global__ __launch_bounds__(256) void xprep_kernel(const float* __restrict__ x) {
    const int bc = blockIdx.x;             // b*CI + ci
    const int b = bc >> 7, ci = bc & 127;
    const int tid = threadIdx.x;
    __shared__ float xp[HW_];
    __shared__ float rs[256];
    __shared__ float esum[4];
    const float* src = x + (size_t)bc * HW_;
    float s = 0.f;
    for (int i = tid; i < HW_; i += 256) {
        float v = src[i];
        xp[i] = v;
        s += v;
    }
    rs[tid] = s;
    __syncthreads();
    for (int off = 128; off > 0; off >>= 1) {
        if (tid < off) rs[tid] += rs[tid + off];
        __syncthreads();
    }
    if (tid == 0) g_pooled[bc] = rs[0] * (1.f / (float)HW_);

    // edge sums: warp0=row0, warp1=row63, warp2=col0, warp3=col63
    if (tid < 128) {
        int w = tid >> 5, l = tid & 31;
        float v;
        if (w == 0)      v = xp[l * 2] + xp[l * 2 + 1];
        else if (w == 1) v = xp[63 * 64 + l * 2] + xp[63 * 64 + l * 2 + 1];
        else if (w == 2) v = xp[(l * 2) * 64] + xp[(l * 2 + 1) * 64];
        else             v = xp[(l * 2) * 64 + 63] + xp[(l * 2 + 1) * 64 + 63];
#pragma unroll
        for (int o = 16; o; o >>= 1) v += __shfl_xor_sync(0xffffffffu, v, o);
        if (l == 0) esum[w] = v;
    }
    __syncthreads();
    if (tid == 0) {
        float T = rs[0];
        float r0 = esum[0], r63 = esum[1], c0 = esum[2], c63 = esum[3];
#pragma unroll
        for (int kh = 0; kh < 3; kh++)
#pragma unroll
            for (int kw = 0; kw < 3; kw++) {
                float sv = T;
                if (kh == 0) sv -= r63;
                if (kh == 2) sv -= r0;
                if (kw == 0) sv -= c63;
                if (kw == 2) sv -= c0;
                if (kh == 0 && kw == 0) sv += xp[63 * 64 + 63];
                if (kh == 0 && kw == 2) sv += xp[63 * 64];
                if (kh == 2 && kw == 0) sv += xp[63];
                if (kh == 2 && kw == 2) sv += xp[0];
                g_S[(size_t)(b * 9 + kh * 3 + kw) * CI_ + ci] = sv;
            }
    }

#pragma unroll
    for (int kw = 0; kw < 3; kw++) {
        __half2* dst = (__half2*)(g_x3 + ((size_t)(kw * B_ + b) * CI_ + ci) * XPLANE);
        for (int idx = tid; idx < XROWS * 32; idx += 256) {
            int row = idx >> 5;            // 0..65 (= gy+1)
            int px = (idx & 31) * 2;
            int gy = row - 1;
            float v0 = 0.f, v1 = 0.f;
            if ((unsigned)gy < (unsigned)H_) {
                int gx0 = px + kw - 1;
                int gx1 = gx0 + 1;
                if ((unsigned)gx0 < (unsigned)W_) v0 = xp[gy * 64 + gx0];
                if ((unsigned)gx1 < (unsigned)W_) v1 = xp[gy * 64 + gx1];
            }
            dst[idx] = __floats2half2_rn(v0, v1);
        }
    }
}

// ---------------- K2: routing MLP + softmax ----------------
__global__ void routing_kernel(const float* __restrict__ rw1, const float* __restrict__ rb1,
                               const float* __restrict__ rw2, const float* __restrict__ rb2,
                               const float* __restrict__ rw3, const float* __restrict__ rb3) {
    int b = blockIdx.x;
    int t = threadIdx.x;  // 128
    __shared__ float pl[CI_], h[E_], s[CI_], lg[E_];
    pl[t] = g_pooled[b * CI_ + t];
    __syncthreads();
    if (t < E_) {
        float a = rb1[t];
        for (int i = 0; i < CI_; i++) a += rw1[t * CI_ + i] * pl[i];
        h[t] = fmaxf(a, 0.f);
    }
    __syncthreads();
    {
        float a = rb2[t];
#pragma unroll
        for (int j = 0; j < E_; j++) a += rw2[t * E_ + j] * h[j];
        s[t] = 1.f / (1.f + expf(-a));
    }
    __syncthreads();
    if (t < E_) {
        float a = rb3[t];
        for (int i = 0; i < CI_; i++) a += rw3[t * CI_ + i] * s[i];
        lg[t] = a;
    }
    __syncthreads();
    if (t == 0) {
        float m = lg[0];
        for (int e = 1; e < E_; e++) m = fmaxf(m, lg[e]);
        float den = 0.f, ex[E_];
        for (int e = 0; e < E_; e++) { ex[e] = expf(lg[e] - m); den += ex[e]; }
        float inv = 1.f / den;
        for (int e = 0; e < E_; e++) g_rw[b * E_ + e] = ex[e] * inv;
    }
}

// ---------------- K3: combine experts -> fp16 [b][r][co][ci] -----------------
__global__ void combine_kernel(const float* __restrict__ experts) {
    int co = blockIdx.x;   // 256
    int ci = threadIdx.x;  // 128
    __shared__ float rws[B_ * E_];
    rws[ci] = g_rw[ci];
    rws[ci + 128] = g_rw[ci + 128];
    __syncthreads();
    float ex[E_ * 9];
#pragma unroll
    for (int e = 0; e < E_; e++) {
        const float* p = experts + (((size_t)e * CO_ + co) * CI_ + ci) * 9;
#pragma unroll
        for (int r = 0; r < 9; r++) ex[e * 9 + r] = p[r];
    }
    for (int b = 0; b < B_; b++) {
#pragma unroll
        for (int r = 0; r < 9; r++) {
            float acc = 0.f;
#pragma unroll
            for (int e = 0; e < E_; e++) acc += rws[b * E_ + e] * ex[e * 9 + r];
            g_wh[((size_t)(b * 9 + r) * CO_ + co) * CI_ + ci] = __float2half_rn(acc);
        }
    }
}

// ---------------- K5: channel attention from analytic pooled output ----------
// pm[b,co] = (1/HW) * sum_{r,ci} W[b,r,co,ci] * S[b,r,ci]; then SE MLP -> g_ca.
__global__ void attn_kernel(const float* __restrict__ aw1, const float* __restrict__ ab1,
                            const float* __restrict__ aw2, const float* __restrict__ ab2) {
    int b = blockIdx.x;
    int t = threadIdx.x;  // 256
    int wid = t >> 5, lane = t & 31;
    __shared__ float pm[CO_], hh[16];
#pragma unroll 1
    for (int it = 0; it < 32; it++) {
        int co = it * 8 + wid;
        float a = 0.f;
#pragma unroll
        for (int r = 0; r < 9; r++) {
            const __half* wp = g_wh + ((size_t)(b * 9 + r) * CO_ + co) * CI_;
            const float* sp = g_S + (size_t)(b * 9 + r) * CI_;
#pragma unroll
            for (int q = 0; q < 4; q++) {
                int ci = lane + q * 32;
                a += __half2float(wp[ci]) * sp[ci];
            }
        }
#pragma unroll
        for (int o = 16; o; o >>= 1) a += __shfl_xor_sync(0xffffffffu, a, o);
        if (lane == 0) pm[co] = a * (1.f / (float)HW_);
    }
    __syncthreads();
    if (t < 16) {
        float a = ab1[t];
        for (int i = 0; i < CO_; i++) a += aw1[t * CO_ + i] * pm[i];
        hh[t] = fmaxf(a, 0.f);
    }
    __syncthreads();
    float a = ab2[t];
#pragma unroll
    for (int j = 0; j < 16; j++) a += aw2[t * 16 + j] * hh[j];
    g_ca[b * CO_ + t] = 1.f / (1.f + expf(-a));
}

// ---------------- K4: implicit-GEMM conv (fp16, M128xN128 CTA, 2 CTA/SM) -----
// grid (32 pixel-tiles, 2 co-halves, 32 b), 256 threads, warp grid 4(M)x2(N),
// warp tile 32x64. K=1152 over 18 stages of 64 ci, 3-stage cp.async ring.
// Epilogue applies channel attention (g_ca) directly.
#define OFF_A  0
#define OFF_B  16384
#define BUFB   32768
#define NSTAGE 3
#define SMEM_TOTAL (NSTAGE * BUFB)  // 98304

__global__ __launch_bounds__(256, 2) void conv_mma_kernel(float* __restrict__ out) {
    extern __shared__ char smem[];
    const uint32_t sb = smem_u32(smem);
    const int tid = threadIdx.x;
    const int wid = tid >> 5;
    const int lane = tid & 31;
    const int tile = blockIdx.x;
    const int nhalf = blockIdx.y;
    const int b = blockIdx.z;
    const int warp_m = wid & 3;   // 0..3 -> 32-pixel chunk
    const int warp_n = wid >> 2;  // 0..1 -> 64-co chunk

    float d[2][8][4];
#pragma unroll
    for (int i = 0; i < 2; i++)
#pragma unroll
        for (int j = 0; j < 8; j++)
#pragma unroll
            for (int q = 0; q < 4; q++) d[i][j][q] = 0.f;

    const __half* whb = g_wh + (size_t)b * 9 * CO_ * CI_ + (size_t)nhalf * 128 * CI_;

    auto stage = [&](int s) {
        const int r = s >> 1;
        const int ci0 = (s & 1) * 64;
        const int kh = r / 3, kw = r - kh * 3;
        const int slot = s % NSTAGE;
        const uint32_t base = sb + (uint32_t)(slot * BUFB);
        // A: 64 ci rows x 128 px (2 gmem rows) fp16 = 16 KB
        const char* asrc = (const char*)(g_x3 + ((size_t)(kw * B_ + b) * CI_ + ci0) * XPLANE +
                                         (size_t)(tile * 2 + kh) * 64);
#pragma unroll
        for (int it = 0; it < 4; it++) {
            int idx = tid + it * 256;
            int ci = idx >> 4, ch = idx & 15;
            cp16(base + OFF_A + (uint32_t)(ci * 256 + ((ch * 16) ^ ((ci & 7) << 4))),
                 asrc + (size_t)ci * (XPLANE * 2) + ch * 16);
        }
        // B: 128 co x 64 ci fp16 = 16 KB
        const char* hsrc = (const char*)(whb + (size_t)r * CO_ * CI_ + ci0);
#pragma unroll
        for (int it = 0; it < 4; it++) {
            int idx = tid + it * 256;
            int co = idx >> 3, ch = idx & 7;
            uint32_t off = (uint32_t)(co * 128 + ((ch * 16) ^ ((co & 7) << 4)));
            cp16(base + OFF_B + off, hsrc + (size_t)co * 256 + ch * 16);
        }
        CP_COMMIT();
    };

    stage(0);
    stage(1);

    // ldmatrix lane components
    const int a_t = lane >> 3, a_rl = lane & 7;               // A x4 trans
    const int b_q = lane >> 3, b_rl = lane & 7;               // B x4
    const int b_nsel = b_q >> 1, b_ksel = b_q & 1;

    for (int s = 0; s < 18; s++) {
        CP_WAIT1();
        __syncthreads();
        if (s < 16) stage(s + 2);
        const uint32_t cur = sb + (uint32_t)((s % NSTAGE) * BUFB);

#pragma unroll
        for (int kc = 0; kc < 4; kc++) {
            uint32_t ah[2][4];
#pragma unroll
            for (int mi = 0; mi < 2; mi++) {
                int k_row = kc * 16 + (a_t >> 1) * 8 + a_rl;
                int m_col = warp_m * 32 + mi * 16 + (a_t & 1) * 8;
                uint32_t addr = cur + OFF_A +
                                (uint32_t)(k_row * 256 + ((m_col * 2) ^ (a_rl << 4)));
                ldsm4t(ah[mi], addr);
            }
#pragma unroll
            for (int njp = 0; njp < 4; njp++) {
                int n = warp_n * 64 + njp * 16 + b_nsel * 8 + b_rl;
                uint32_t kb = (uint32_t)(kc * 32 + b_ksel * 16);
                uint32_t off = (uint32_t)(n * 128) + (kb ^ (uint32_t)(b_rl << 4));
                uint32_t bh[4];
                ldsm4(bh, cur + OFF_B + off);
#pragma unroll
                for (int j = 0; j < 2; j++)
#pragma unroll
                    for (int mi = 0; mi < 2; mi++)
                        mma_f16(d[mi][njp * 2 + j], ah[mi], bh + 2 * j);
            }
        }
    }

    // ---- epilogue: transpose through smem (stride 132), apply ca, write ----
    __syncthreads();
    float* red = (float*)smem;  // [128 co][132] = 67584 B
#pragma unroll
    for (int mi = 0; mi < 2; mi++)
#pragma unroll
        for (int ni = 0; ni < 8; ni++) {
            int m = warp_m * 32 + mi * 16 + (lane >> 2);
            int n = warp_n * 64 + ni * 8 + 2 * (lane & 3);
            const float* a = d[mi][ni];
            red[n * 132 + m] = a[0];
            red[(n + 1) * 132 + m] = a[1];
            red[n * 132 + m + 8] = a[2];
            red[(n + 1) * 132 + m + 8] = a[3];
        }
    __syncthreads();
    {
        int col = tid >> 1, half = tid & 1;       // col 0..127 local
        int co = nhalf * 128 + col;
        float c = g_ca[b * CO_ + co];
        const float4* rp = (const float4*)(red + col * 132 + half * 64);
        float* op = out + ((size_t)(b * CO_ + co)) * HW_ + tile * 128 + half * 64;
#pragma unroll
        for (int i = 0; i < 16; i++) {
            float4 v = rp[i];
            v.x *= c; v.y *= c; v.z *= c; v.w *= c;
            ((float4*)op)[i] = v;
        }
    }
}

// ---------------- launch ----------------
extern "C" void kernel_launch(void* const* d_in, const int* in_sizes, int n_in,
                              void* d_out, int out_size) {
    const float* x       = (const float*)d_in[0];
    const float* experts = (const float*)d_in[1];
    const float* rw1 = (const float*)d_in[2];
    const float* rb1 = (const float*)d_in[3];
    const float* rw2 = (const float*)d_in[4];
    const float* rb2 = (const float*)d_in[5];
    const float* rw3 = (const float*)d_in[6];
    const float* rb3 = (const float*)d_in[7];
    const float* aw1 = (const float*)d_in[8];
    const float* ab1 = (const float*)d_in[9];
    const float* aw2 = (const float*)d_in[10];
    const float* ab2 = (const float*)d_in[11];
    float* out = (float*)d_out;

    cudaFuncSetAttribute(conv_mma_kernel, cudaFuncAttributeMaxDynamicSharedMemorySize,
                         SMEM_TOTAL);

    xprep_kernel<<<B_ * CI_, 256>>>(x);
    routing_kernel<<<B_, 128>>>(rw1, rb1, rw2, rb2, rw3, rb3);
    combine_kernel<<<CO_, 128>>>(experts);
    attn_kernel<<<B_, 256>>>(aw1, ab1, aw2, ab2);
    conv_mma_kernel<<<dim3(32, 2, B_), 256, SMEM_TOTAL>>>(out);
}

// round 10
// speedup vs baseline: 1.0838x; 1.0838x over previous
#include <cuda_runtime.h>
#include <cuda_fp16.h>
#include <math.h>
#include <stdint.h>

#define B_  32
#define CI_ 128
#define CO_ 256
#define H_  64
#define W_  64
#define E_  8
#define HW_ 4096
#define XROWS 66
#define XPLANE (XROWS * 64)   // 4224 halves per (kw,b,ci)

// ---------------- scratch ----------------
__device__ float g_pooled[B_ * CI_];
__device__ float g_rw[B_ * E_];
__device__ __half g_x3[(size_t)3 * B_ * CI_ * XPLANE];      // kw-shifted, halo-padded x (fp16)
__device__ __half g_wh[(size_t)B_ * 9 * CO_ * CI_];         // [b][r][co][ci]
__device__ float g_S[(size_t)B_ * 9 * CI_];                 // window sums of x per (b,r,ci)
__device__ float g_pm[(size_t)B_ * CO_];                    // pooled conv output (analytic)
__device__ float g_ca[B_ * CO_];

// ---------------- PTX helpers (base sm_103 PTX only) ----------------
__device__ __forceinline__ uint32_t smem_u32(const void* p) {
    uint32_t a;
    asm("{ .reg .u64 t; cvta.to.shared.u64 t, %1; cvt.u32.u64 %0, t; }" : "=r"(a) : "l"(p));
    return a;
}
__device__ __forceinline__ void ldsm4(uint32_t* r, uint32_t addr) {
    asm volatile("ldmatrix.sync.aligned.m8n8.x4.shared.b16 {%0,%1,%2,%3}, [%4];"
                 : "=r"(r[0]), "=r"(r[1]), "=r"(r[2]), "=r"(r[3]) : "r"(addr));
}
__device__ __forceinline__ void ldsm4t(uint32_t* r, uint32_t addr) {
    asm volatile("ldmatrix.sync.aligned.m8n8.x4.trans.shared.b16 {%0,%1,%2,%3}, [%4];"
                 : "=r"(r[0]), "=r"(r[1]), "=r"(r[2]), "=r"(r[3]) : "r"(addr));
}
__device__ __forceinline__ void mma_f16(float* d, const uint32_t* a, const uint32_t* b) {
    asm volatile(
        "mma.sync.aligned.m16n8k16.row.col.f32.f16.f16.f32 "
        "{%0,%1,%2,%3}, {%4,%5,%6,%7}, {%8,%9}, {%0,%1,%2,%3};"
        : "+f"(d[0]), "+f"(d[1]), "+f"(d[2]), "+f"(d[3])
        : "r"(a[0]), "r"(a[1]), "r"(a[2]), "r"(a[3]), "r"(b[0]), "r"(b[1]));
}
__device__ __forceinline__ void cp16(uint32_t dst, const void* src) {
    asm volatile("cp.async.cg.shared.global [%0], [%1], 16;" :: "r"(dst), "l"(src) : "memory");
}
#define CP_COMMIT() asm volatile("cp.async.commit_group;" ::: "memory")
#define CP_WAIT1()  asm volatile("cp.async.wait_group 1;" ::: "memory")

// ---------------- K1: x -> fp16 shifted copies + pooled mean + window sums ---
__global__ __launch_bounds__(256) void xprep_kernel(const float* __restrict__ x) {
    const int bc = blockIdx.x;             // b*CI + ci
    const int b = bc >> 7, ci = bc & 127;
    const int tid = threadIdx.x;
    __shared__ float xp[HW_];
    __shared__ float rs[256];
    __shared__ float esum[4];
    const float* src = x + (size_t)bc * HW_;
    float s = 0.f;
    for (int i = tid; i < HW_; i += 256) {
        float v = src[i];
        xp[i] = v;
        s += v;
    }
    rs[tid] = s;
    __syncthreads();
    for (int off = 128; off > 0; off >>= 1) {
        if (tid < off) rs[tid] += rs[tid + off];
        __syncthreads();
    }
    if (tid == 0) g_pooled[bc] = rs[0] * (1.f / (float)HW_);

    // edge sums: warp0=row0, warp1=row63, warp2=col0, warp3=col63
    if (tid < 128) {
        int w = tid >> 5, l = tid & 31;
        float v;
        if (w == 0)      v = xp[l * 2] + xp[l * 2 + 1];
        else if (w == 1) v = xp[63 * 64 + l * 2] + xp[63 * 64 + l * 2 + 1];
        else if (w == 2) v = xp[(l * 2) * 64] + xp[(l * 2 + 1) * 64];
        else             v = xp[(l * 2) * 64 + 63] + xp[(l * 2 + 1) * 64 + 63];
#pragma unroll
        for (int o = 16; o; o >>= 1) v += __shfl_xor_sync(0xffffffffu, v, o);
        if (l == 0) esum[w] = v;
    }
    __syncthreads();
    if (tid == 0) {
        float T = rs[0];
        float r0 = esum[0], r63 = esum[1], c0 = esum[2], c63 = esum[3];
#pragma unroll
        for (int kh = 0; kh < 3; kh++)
#pragma unroll
            for (int kw = 0; kw < 3; kw++) {
                float sv = T;
                if (kh == 0) sv -= r63;
                if (kh == 2) sv -= r0;
                if (kw == 0) sv -= c63;
                if (kw == 2) sv -= c0;
                if (kh == 0 && kw == 0) sv += xp[63 * 64 + 63];
                if (kh == 0 && kw == 2) sv += xp[63 * 64];
                if (kh == 2 && kw == 0) sv += xp[63];
                if (kh == 2 && kw == 2) sv += xp[0];
                g_S[(size_t)(b * 9 + kh * 3 + kw) * CI_ + ci] = sv;
            }
    }

#pragma unroll
    for (int kw = 0; kw < 3; kw++) {
        __half2* dst = (__half2*)(g_x3 + ((size_t)(kw * B_ + b) * CI_ + ci) * XPLANE);
        for (int idx = tid; idx < XROWS * 32; idx += 256) {
            int row = idx >> 5;            // 0..65 (= gy+1)
            int px = (idx & 31) * 2;
            int gy = row - 1;
            float v0 = 0.f, v1 = 0.f;
            if ((unsigned)gy < (unsigned)H_) {
                int gx0 = px + kw - 1;
                int gx1 = gx0 + 1;
                if ((unsigned)gx0 < (unsigned)W_) v0 = xp[gy * 64 + gx0];
                if ((unsigned)gx1 < (unsigned)W_) v1 = xp[gy * 64 + gx1];
            }
            dst[idx] = __floats2half2_rn(v0, v1);
        }
    }
}

// ---------------- K2: routing MLP + softmax ----------------
__global__ void routing_kernel(const float* __restrict__ rw1, const float* __restrict__ rb1,
                               const float* __restrict__ rw2, const float* __restrict__ rb2,
                               const float* __restrict__ rw3, const float* __restrict__ rb3) {
    int b = blockIdx.x;
    int t = threadIdx.x;  // 128
    __shared__ float pl[CI_], h[E_], s[CI_], lg[E_];
    pl[t] = g_pooled[b * CI_ + t];
    __syncthreads();
    if (t < E_) {
        float a = rb1[t];
        for (int i = 0; i < CI_; i++) a += rw1[t * CI_ + i] * pl[i];
        h[t] = fmaxf(a, 0.f);
    }
    __syncthreads();
    {
        float a = rb2[t];
#pragma unroll
        for (int j = 0; j < E_; j++) a += rw2[t * E_ + j] * h[j];
        s[t] = 1.f / (1.f + expf(-a));
    }
    __syncthreads();
    if (t < E_) {
        float a = rb3[t];
        for (int i = 0; i < CI_; i++) a += rw3[t * CI_ + i] * s[i];
        lg[t] = a;
    }
    __syncthreads();
    if (t == 0) {
        float m = lg[0];
        for (int e = 1; e < E_; e++) m = fmaxf(m, lg[e]);
        float den = 0.f, ex[E_];
        for (int e = 0; e < E_; e++) { ex[e] = expf(lg[e] - m); den += ex[e]; }
        float inv = 1.f / den;
        for (int e = 0; e < E_; e++) g_rw[b * E_ + e] = ex[e] * inv;
    }
}

// ---------------- K3: combine experts -> fp16 W + analytic pooled output -----
__global__ void combine_kernel(const float* __restrict__ experts) {
    int co = blockIdx.x;   // 256
    int ci = threadIdx.x;  // 128
    int lane = ci & 31, w = ci >> 5;
    __shared__ float rws[B_ * E_];
    __shared__ float red4[4][B_];
    rws[ci] = g_rw[ci];
    rws[ci + 128] = g_rw[ci + 128];
    __syncthreads();
    float ex[E_ * 9];
#pragma unroll
    for (int e = 0; e < E_; e++) {
        const float* p = experts + (((size_t)e * CO_ + co) * CI_ + ci) * 9;
#pragma unroll
        for (int r = 0; r < 9; r++) ex[e * 9 + r] = p[r];
    }
    for (int b = 0; b < B_; b++) {
        float p = 0.f;
#pragma unroll
        for (int r = 0; r < 9; r++) {
            float acc = 0.f;
#pragma unroll
            for (int e = 0; e < E_; e++) acc += rws[b * E_ + e] * ex[e * 9 + r];
            g_wh[((size_t)(b * 9 + r) * CO_ + co) * CI_ + ci] = __float2half_rn(acc);
            p += acc * g_S[(size_t)(b * 9 + r) * CI_ + ci];
        }
#pragma unroll
        for (int o = 16; o; o >>= 1) p += __shfl_xor_sync(0xffffffffu, p, o);
        if (lane == 0) red4[w][b] = p;
    }
    __syncthreads();
    if (ci < B_)
        g_pm[(size_t)ci * CO_ + co] =
            (red4[0][ci] + red4[1][ci] + red4[2][ci] + red4[3][ci]) * (1.f / (float)HW_);
}

// ---------------- K5: channel attention SE MLP (pm precomputed) --------------
__global__ void attn_kernel(const float* __restrict__ aw1, const float* __restrict__ ab1,
                            const float* __restrict__ aw2, const float* __restrict__ ab2) {
    int b = blockIdx.x;
    int t = threadIdx.x;  // 256
    __shared__ float pm[CO_], hh[16];
    pm[t] = g_pm[(size_t)b * CO_ + t];
    __syncthreads();
    if (t < 16) {
        float a = ab1[t];
        for (int i = 0; i < CO_; i++) a += aw1[t * CO_ + i] * pm[i];
        hh[t] = fmaxf(a, 0.f);
    }
    __syncthreads();
    float a = ab2[t];
#pragma unroll
    for (int j = 0; j < 16; j++) a += aw2[t * 16 + j] * hh[j];
    g_ca[b * CO_ + t] = 1.f / (1.f + expf(-a));
}

// ---------------- K4: implicit-GEMM conv (fp16, M128xN128 CTA, 2 CTA/SM) -----
// grid (32 pixel-tiles, 2 co-halves, 32 b), 256 threads, warp grid 4(M)x2(N),
// warp tile 32x64. K=1152 over 18 stages of 64 ci, 3-stage cp.async ring.
// Epilogue applies channel attention (g_ca) directly.
#define OFF_A  0
#define OFF_B  16384
#define BUFB   32768
#define NSTAGE 3
#define SMEM_TOTAL (NSTAGE * BUFB)  // 98304

__global__ __launch_bounds__(256, 2) void conv_mma_kernel(float* __restrict__ out) {
    extern __shared__ char smem[];
    const uint32_t sb = smem_u32(smem);
    const int tid = threadIdx.x;
    const int wid = tid >> 5;
    const int lane = tid & 31;
    const int tile = blockIdx.x;
    const int nhalf = blockIdx.y;
    const int b = blockIdx.z;
    const int warp_m = wid & 3;   // 0..3 -> 32-pixel chunk
    const int warp_n = wid >> 2;  // 0..1 -> 64-co chunk

    float d[2][8][4];
#pragma unroll
    for (int i = 0; i < 2; i++)
#pragma unroll
        for (int j = 0; j < 8; j++)
#pragma unroll
            for (int q = 0; q < 4; q++) d[i][j][q] = 0.f;

    const __half* whb = g_wh + (size_t)b * 9 * CO_ * CI_ + (size_t)nhalf * 128 * CI_;

    auto stage = [&](int s) {
        const int r = s >> 1;
        const int ci0 = (s & 1) * 64;
        const int kh = r / 3, kw = r - kh * 3;
        const int slot = s % NSTAGE;
        const uint32_t base = sb + (uint32_t)(slot * BUFB);
        // A: 64 ci rows x 128 px (2 gmem rows) fp16 = 16 KB
        const char* asrc = (const char*)(g_x3 + ((size_t)(kw * B_ + b) * CI_ + ci0) * XPLANE +
                                         (size_t)(tile * 2 + kh) * 64);
#pragma unroll
        for (int it = 0; it < 4; it++) {
            int idx = tid + it * 256;
            int ci = idx >> 4, ch = idx & 15;
            cp16(base + OFF_A + (uint32_t)(ci * 256 + ((ch * 16) ^ ((ci & 7) << 4))),
                 asrc + (size_t)ci * (XPLANE * 2) + ch * 16);
        }
        // B: 128 co x 64 ci fp16 = 16 KB
        const char* hsrc = (const char*)(whb + (size_t)r * CO_ * CI_ + ci0);
#pragma unroll
        for (int it = 0; it < 4; it++) {
            int idx = tid + it * 256;
            int co = idx >> 3, ch = idx & 7;
            uint32_t off = (uint32_t)(co * 128 + ((ch * 16) ^ ((co & 7) << 4)));
            cp16(base + OFF_B + off, hsrc + (size_t)co * 256 + ch * 16);
        }
        CP_COMMIT();
    };

    stage(0);
    stage(1);

    // ldmatrix lane components
    const int a_t = lane >> 3, a_rl = lane & 7;               // A x4 trans
    const int b_q = lane >> 3, b_rl = lane & 7;               // B x4
    const int b_nsel = b_q >> 1, b_ksel = b_q & 1;

    for (int s = 0; s < 18; s++) {
        CP_WAIT1();
        __syncthreads();
        if (s < 16) stage(s + 2);
        const uint32_t cur = sb + (uint32_t)((s % NSTAGE) * BUFB);

#pragma unroll
        for (int kc = 0; kc < 4; kc++) {
            uint32_t ah[2][4];
#pragma unroll
            for (int mi = 0; mi < 2; mi++) {
                int k_row = kc * 16 + (a_t >> 1) * 8 + a_rl;
                int m_col = warp_m * 32 + mi * 16 + (a_t & 1) * 8;
                uint32_t addr = cur + OFF_A +
                                (uint32_t)(k_row * 256 + ((m_col * 2) ^ (a_rl << 4)));
                ldsm4t(ah[mi], addr);
            }
#pragma unroll
            for (int njp = 0; njp < 4; njp++) {
                int n = warp_n * 64 + njp * 16 + b_nsel * 8 + b_rl;
                uint32_t kb = (uint32_t)(kc * 32 + b_ksel * 16);
                uint32_t off = (uint32_t)(n * 128) + (kb ^ (uint32_t)(b_rl << 4));
                uint32_t bh[4];
                ldsm4(bh, cur + OFF_B + off);
#pragma unroll
                for (int j = 0; j < 2; j++)
#pragma unroll
                    for (int mi = 0; mi < 2; mi++)
                        mma_f16(d[mi][njp * 2 + j], ah[mi], bh + 2 * j);
            }
        }
    }

    // ---- epilogue: transpose through smem (stride 132), apply ca, write ----
    __syncthreads();
    float* red = (float*)smem;  // [128 co][132] = 67584 B
#pragma unroll
    for (int mi = 0; mi < 2; mi++)
#pragma unroll
        for (int ni = 0; ni < 8; ni++) {
            int m = warp_m * 32 + mi * 16 + (lane >> 2);
            int n = warp_n * 64 + ni * 8 + 2 * (lane & 3);
            const float* a = d[mi][ni];
            red[n * 132 + m] = a[0];
            red[(n + 1) * 132 + m] = a[1];
            red[n * 132 + m + 8] = a[2];
            red[(n + 1) * 132 + m + 8] = a[3];
        }
    __syncthreads();
    {
        int col = tid >> 1, half = tid & 1;       // col 0..127 local
        int co = nhalf * 128 + col;
        float c = g_ca[b * CO_ + co];
        const float4* rp = (const float4*)(red + col * 132 + half * 64);
        float* op = out + ((size_t)(b * CO_ + co)) * HW_ + tile * 128 + half * 64;
#pragma unroll
        for (int i = 0; i < 16; i++) {
            float4 v = rp[i];
            v.x *= c; v.y *= c; v.z *= c; v.w *= c;
            ((float4*)op)[i] = v;
        }
    }
}

// ---------------- launch ----------------
extern "C" void kernel_launch(void* const* d_in, const int* in_sizes, int n_in,
                              void* d_out, int out_size) {
    const float* x       = (const float*)d_in[0];
    const float* experts = (const float*)d_in[1];
    const float* rw1 = (const float*)d_in[2];
    const float* rb1 = (const float*)d_in[3];
    const float* rw2 = (const float*)d_in[4];
    const float* rb2 = (const float*)d_in[5];
    const float* rw3 = (const float*)d_in[6];
    const float* rb3 = (const float*)d_in[7];
    const float* aw1 = (const float*)d_in[8];
    const float* ab1 = (const float*)d_in[9];
    const float* aw2 = (const float*)d_in[10];
    const float* ab2 = (const float*)d_in[11];
    float* out = (float*)d_out;

    cudaFuncSetAttribute(conv_mma_kernel, cudaFuncAttributeMaxDynamicSharedMemorySize,
                         SMEM_TOTAL);

    xprep_kernel<<<B_ * CI_, 256>>>(x);
    routing_kernel<<<B_, 128>>>(rw1, rb1, rw2, rb2, rw3, rb3);
    combine_kernel<<<CO_, 128>>>(experts);
    attn_kernel<<<B_, 256>>>(aw1, ab1, aw2, ab2);
    conv_mma_kernel<<<dim3(32, 2, B_), 256, SMEM_TOTAL>>>(out);
}

// round 11
// speedup vs baseline: 1.2225x; 1.1280x over previous
#include <cuda_runtime.h>
#include <cuda_fp16.h>
#include <math.h>
#include <stdint.h>

#define B_  32
#define CI_ 128
#define CO_ 256
#define H_  64
#define W_  64
#define E_  8
#define HW_ 4096
#define XROWS 66
#define XPLANE (XROWS * 64)   // 4224 halves per (kw,b,ci)

// ---------------- scratch ----------------
__device__ float g_pooled[B_ * CI_];
__device__ float g_rw[B_ * E_];
__device__ __half g_x3[(size_t)3 * B_ * CI_ * XPLANE];      // kw-shifted, halo-padded x (fp16)
__device__ __half g_wh[(size_t)B_ * 9 * CO_ * CI_];         // [b][r][co][ci]
__device__ float g_S[(size_t)B_ * 9 * CI_];                 // window sums of x per (b,r,ci)
__device__ float g_pm[(size_t)B_ * CO_];                    // pooled conv output (analytic)
__device__ float g_ca[B_ * CO_];

// ---------------- PTX helpers (base sm_103 PTX only) ----------------
__device__ __forceinline__ uint32_t smem_u32(const void* p) {
    uint32_t a;
    asm("{ .reg .u64 t; cvta.to.shared.u64 t, %1; cvt.u32.u64 %0, t; }" : "=r"(a) : "l"(p));
    return a;
}
__device__ __forceinline__ void ldsm4(uint32_t* r, uint32_t addr) {
    asm volatile("ldmatrix.sync.aligned.m8n8.x4.shared.b16 {%0,%1,%2,%3}, [%4];"
                 : "=r"(r[0]), "=r"(r[1]), "=r"(r[2]), "=r"(r[3]) : "r"(addr));
}
__device__ __forceinline__ void ldsm4t(uint32_t* r, uint32_t addr) {
    asm volatile("ldmatrix.sync.aligned.m8n8.x4.trans.shared.b16 {%0,%1,%2,%3}, [%4];"
                 : "=r"(r[0]), "=r"(r[1]), "=r"(r[2]), "=r"(r[3]) : "r"(addr));
}
__device__ __forceinline__ void mma_f16(float* d, const uint32_t* a, const uint32_t* b) {
    asm volatile(
        "mma.sync.aligned.m16n8k16.row.col.f32.f16.f16.f32 "
        "{%0,%1,%2,%3}, {%4,%5,%6,%7}, {%8,%9}, {%0,%1,%2,%3};"
        : "+f"(d[0]), "+f"(d[1]), "+f"(d[2]), "+f"(d[3])
        : "r"(a[0]), "r"(a[1]), "r"(a[2]), "r"(a[3]), "r"(b[0]), "r"(b[1]));
}
__device__ __forceinline__ void cp16(uint32_t dst, const void* src) {
    asm volatile("cp.async.cg.shared.global [%0], [%1], 16;" :: "r"(dst), "l"(src) : "memory");
}
#define CP_COMMIT() asm volatile("cp.async.commit_group;" ::: "memory")
#define CP_WAIT1()  asm volatile("cp.async.wait_group 1;" ::: "memory")

__device__ __forceinline__ float warp_sum(float v) {
#pragma unroll
    for (int o = 16; o; o >>= 1) v += __shfl_xor_sync(0xffffffffu, v, o);
    return v;
}

// ---------------- K1: x -> fp16 shifted copies + pooled mean + window sums ---
__global__ __launch_bounds__(256) void xprep_kernel(const float* __restrict__ x) {
    const int bc = blockIdx.x;             // b*CI + ci
    const int b = bc >> 7, ci = bc & 127;
    const int tid = threadIdx.x;
    __shared__ float xp[HW_];
    __shared__ float rs[256];
    __shared__ float esum[4];
    const float* src = x + (size_t)bc * HW_;
    float s = 0.f;
    for (int i = tid; i < HW_; i += 256) {
        float v = src[i];
        xp[i] = v;
        s += v;
    }
    rs[tid] = s;
    __syncthreads();
    for (int off = 128; off > 0; off >>= 1) {
        if (tid < off) rs[tid] += rs[tid + off];
        __syncthreads();
    }
    if (tid == 0) g_pooled[bc] = rs[0] * (1.f / (float)HW_);

    // edge sums: warp0=row0, warp1=row63, warp2=col0, warp3=col63
    if (tid < 128) {
        int w = tid >> 5, l = tid & 31;
        float v;
        if (w == 0)      v = xp[l * 2] + xp[l * 2 + 1];
        else if (w == 1) v = xp[63 * 64 + l * 2] + xp[63 * 64 + l * 2 + 1];
        else if (w == 2) v = xp[(l * 2) * 64] + xp[(l * 2 + 1) * 64];
        else             v = xp[(l * 2) * 64 + 63] + xp[(l * 2 + 1) * 64 + 63];
        v = warp_sum(v);
        if (l == 0) esum[w] = v;
    }
    __syncthreads();
    if (tid == 0) {
        float T = rs[0];
        float r0 = esum[0], r63 = esum[1], c0 = esum[2], c63 = esum[3];
#pragma unroll
        for (int kh = 0; kh < 3; kh++)
#pragma unroll
            for (int kw = 0; kw < 3; kw++) {
                float sv = T;
                if (kh == 0) sv -= r63;
                if (kh == 2) sv -= r0;
                if (kw == 0) sv -= c63;
                if (kw == 2) sv -= c0;
                if (kh == 0 && kw == 0) sv += xp[63 * 64 + 63];
                if (kh == 0 && kw == 2) sv += xp[63 * 64];
                if (kh == 2 && kw == 0) sv += xp[63];
                if (kh == 2 && kw == 2) sv += xp[0];
                g_S[(size_t)(b * 9 + kh * 3 + kw) * CI_ + ci] = sv;
            }
    }

#pragma unroll
    for (int kw = 0; kw < 3; kw++) {
        __half2* dst = (__half2*)(g_x3 + ((size_t)(kw * B_ + b) * CI_ + ci) * XPLANE);
        for (int idx = tid; idx < XROWS * 32; idx += 256) {
            int row = idx >> 5;            // 0..65 (= gy+1)
            int px = (idx & 31) * 2;
            int gy = row - 1;
            float v0 = 0.f, v1 = 0.f;
            if ((unsigned)gy < (unsigned)H_) {
                int gx0 = px + kw - 1;
                int gx1 = gx0 + 1;
                if ((unsigned)gx0 < (unsigned)W_) v0 = xp[gy * 64 + gx0];
                if ((unsigned)gx1 < (unsigned)W_) v1 = xp[gy * 64 + gx1];
            }
            dst[idx] = __floats2half2_rn(v0, v1);
        }
    }
}

// ---------------- K2: routing MLP + softmax (warp-parallel dots) -------------
__global__ void routing_kernel(const float* __restrict__ rw1, const float* __restrict__ rb1,
                               const float* __restrict__ rw2, const float* __restrict__ rb2,
                               const float* __restrict__ rw3, const float* __restrict__ rb3) {
    int b = blockIdx.x;
    int t = threadIdx.x;  // 128 = 4 warps
    int wid = t >> 5, lane = t & 31;
    __shared__ float pl[CI_], h[E_], s[CI_], lg[E_];
    pl[t] = g_pooled[b * CI_ + t];
    __syncthreads();
#pragma unroll
    for (int k = 0; k < 2; k++) {
        int e = wid * 2 + k;
        float a = 0.f;
#pragma unroll
        for (int q = 0; q < 4; q++) {
            int i = lane + q * 32;
            a += rw1[e * CI_ + i] * pl[i];
        }
        a = warp_sum(a);
        if (lane == 0) h[e] = fmaxf(a + rb1[e], 0.f);
    }
    __syncthreads();
    {
        float a = rb2[t];
#pragma unroll
        for (int j = 0; j < E_; j++) a += rw2[t * E_ + j] * h[j];
        s[t] = 1.f / (1.f + expf(-a));
    }
    __syncthreads();
#pragma unroll
    for (int k = 0; k < 2; k++) {
        int e = wid * 2 + k;
        float a = 0.f;
#pragma unroll
        for (int q = 0; q < 4; q++) {
            int i = lane + q * 32;
            a += rw3[e * CI_ + i] * s[i];
        }
        a = warp_sum(a);
        if (lane == 0) lg[e] = a + rb3[e];
    }
    __syncthreads();
    if (t == 0) {
        float m = lg[0];
        for (int e = 1; e < E_; e++) m = fmaxf(m, lg[e]);
        float den = 0.f, ex[E_];
        for (int e = 0; e < E_; e++) { ex[e] = expf(lg[e] - m); den += ex[e]; }
        float inv = 1.f / den;
        for (int e = 0; e < E_; e++) g_rw[b * E_ + e] = ex[e] * inv;
    }
}

// ---------------- K3: combine experts -> fp16 W + analytic pooled output -----
// grid (256 co, 4 b-groups), 128 threads; each block handles 8 b's.
__global__ void combine_kernel(const float* __restrict__ experts) {
    int co = blockIdx.x;   // 256
    int bg = blockIdx.y;   // 0..3 -> b in [bg*8, bg*8+8)
    int ci = threadIdx.x;  // 128
    int lane = ci & 31, w = ci >> 5;
    __shared__ float rws[8 * E_];
    __shared__ float red4[4][8];
    if (ci < 64) rws[ci] = g_rw[bg * 64 + ci];
    __syncthreads();
    float ex[E_ * 9];
#pragma unroll
    for (int e = 0; e < E_; e++) {
        const float* p = experts + (((size_t)e * CO_ + co) * CI_ + ci) * 9;
#pragma unroll
        for (int r = 0; r < 9; r++) ex[e * 9 + r] = p[r];
    }
#pragma unroll
    for (int bl = 0; bl < 8; bl++) {
        int b = bg * 8 + bl;
        float p = 0.f;
#pragma unroll
        for (int r = 0; r < 9; r++) {
            float acc = 0.f;
#pragma unroll
            for (int e = 0; e < E_; e++) acc += rws[bl * E_ + e] * ex[e * 9 + r];
            g_wh[((size_t)(b * 9 + r) * CO_ + co) * CI_ + ci] = __float2half_rn(acc);
            p += acc * g_S[(size_t)(b * 9 + r) * CI_ + ci];
        }
        p = warp_sum(p);
        if (lane == 0) red4[w][bl] = p;
    }
    __syncthreads();
    if (ci < 8)
        g_pm[(size_t)(bg * 8 + ci) * CO_ + co] =
            (red4[0][ci] + red4[1][ci] + red4[2][ci] + red4[3][ci]) * (1.f / (float)HW_);
}

// ---------------- K5: channel attention SE MLP (warp-parallel hidden) --------
__global__ void attn_kernel(const float* __restrict__ aw1, const float* __restrict__ ab1,
                            const float* __restrict__ aw2, const float* __restrict__ ab2) {
    int b = blockIdx.x;
    int t = threadIdx.x;  // 256 = 8 warps
    int wid = t >> 5, lane = t & 31;
    __shared__ float pm[CO_], hh[16];
    pm[t] = g_pm[(size_t)b * CO_ + t];
    __syncthreads();
#pragma unroll
    for (int k = 0; k < 2; k++) {
        int hidx = wid * 2 + k;
        float a = 0.f;
#pragma unroll
        for (int q = 0; q < 8; q++) {
            int i = lane + q * 32;
            a += aw1[hidx * CO_ + i] * pm[i];
        }
        a = warp_sum(a);
        if (lane == 0) hh[hidx] = fmaxf(a + ab1[hidx], 0.f);
    }
    __syncthreads();
    float a = ab2[t];
#pragma unroll
    for (int j = 0; j < 16; j++) a += aw2[t * 16 + j] * hh[j];
    g_ca[b * CO_ + t] = 1.f / (1.f + expf(-a));
}

// ---------------- K4: implicit-GEMM conv (fp16, M128xN128 CTA, 2 CTA/SM) -----
// grid (32 pixel-tiles, 2 co-halves, 32 b), 256 threads, warp grid 4(M)x2(N),
// warp tile 32x64. K=1152 over 18 stages of 64 ci, 3-stage cp.async ring.
// Epilogue applies channel attention (g_ca) directly.
#define OFF_A  0
#define OFF_B  16384
#define BUFB   32768
#define NSTAGE 3
#define SMEM_TOTAL (NSTAGE * BUFB)  // 98304

__global__ __launch_bounds__(256, 2) void conv_mma_kernel(float* __restrict__ out) {
    extern __shared__ char smem[];
    const uint32_t sb = smem_u32(smem);
    const int tid = threadIdx.x;
    const int wid = tid >> 5;
    const int lane = tid & 31;
    const int tile = blockIdx.x;
    const int nhalf = blockIdx.y;
    const int b = blockIdx.z;
    const int warp_m = wid & 3;   // 0..3 -> 32-pixel chunk
    const int warp_n = wid >> 2;  // 0..1 -> 64-co chunk

    float d[2][8][4];
#pragma unroll
    for (int i = 0; i < 2; i++)
#pragma unroll
        for (int j = 0; j < 8; j++)
#pragma unroll
            for (int q = 0; q < 4; q++) d[i][j][q] = 0.f;

    const __half* whb = g_wh + (size_t)b * 9 * CO_ * CI_ + (size_t)nhalf * 128 * CI_;

    auto stage = [&](int s) {
        const int r = s >> 1;
        const int ci0 = (s & 1) * 64;
        const int kh = r / 3, kw = r - kh * 3;
        const int slot = s % NSTAGE;
        const uint32_t base = sb + (uint32_t)(slot * BUFB);
        // A: 64 ci rows x 128 px (2 gmem rows) fp16 = 16 KB
        const char* asrc = (const char*)(g_x3 + ((size_t)(kw * B_ + b) * CI_ + ci0) * XPLANE +
                                         (size_t)(tile * 2 + kh) * 64);
#pragma unroll
        for (int it = 0; it < 4; it++) {
            int idx = tid + it * 256;
            int ci = idx >> 4, ch = idx & 15;
            cp16(base + OFF_A + (uint32_t)(ci * 256 + ((ch * 16) ^ ((ci & 7) << 4))),
                 asrc + (size_t)ci * (XPLANE * 2) + ch * 16);
        }
        // B: 128 co x 64 ci fp16 = 16 KB
        const char* hsrc = (const char*)(whb + (size_t)r * CO_ * CI_ + ci0);
#pragma unroll
        for (int it = 0; it < 4; it++) {
            int idx = tid + it * 256;
            int co = idx >> 3, ch = idx & 7;
            uint32_t off = (uint32_t)(co * 128 + ((ch * 16) ^ ((co & 7) << 4)));
            cp16(base + OFF_B + off, hsrc + (size_t)co * 256 + ch * 16);
        }
        CP_COMMIT();
    };

    stage(0);
    stage(1);

    // ldmatrix lane components
    const int a_t = lane >> 3, a_rl = lane & 7;               // A x4 trans
    const int b_q = lane >> 3, b_rl = lane & 7;               // B x4
    const int b_nsel = b_q >> 1, b_ksel = b_q & 1;

    for (int s = 0; s < 18; s++) {
        CP_WAIT1();
        __syncthreads();
        if (s < 16) stage(s + 2);
        const uint32_t cur = sb + (uint32_t)((s % NSTAGE) * BUFB);

#pragma unroll
        for (int kc = 0; kc < 4; kc++) {
            uint32_t ah[2][4];
#pragma unroll
            for (int mi = 0; mi < 2; mi++) {
                int k_row = kc * 16 + (a_t >> 1) * 8 + a_rl;
                int m_col = warp_m * 32 + mi * 16 + (a_t & 1) * 8;
                uint32_t addr = cur + OFF_A +
                                (uint32_t)(k_row * 256 + ((m_col * 2) ^ (a_rl << 4)));
                ldsm4t(ah[mi], addr);
            }
#pragma unroll
            for (int njp = 0; njp < 4; njp++) {
                int n = warp_n * 64 + njp * 16 + b_nsel * 8 + b_rl;
                uint32_t kb = (uint32_t)(kc * 32 + b_ksel * 16);
                uint32_t off = (uint32_t)(n * 128) + (kb ^ (uint32_t)(b_rl << 4));
                uint32_t bh[4];
                ldsm4(bh, cur + OFF_B + off);
#pragma unroll
                for (int j = 0; j < 2; j++)
#pragma unroll
                    for (int mi = 0; mi < 2; mi++)
                        mma_f16(d[mi][njp * 2 + j], ah[mi], bh + 2 * j);
            }
        }
    }

    // ---- epilogue: transpose through smem (stride 132), apply ca, write ----
    __syncthreads();
    float* red = (float*)smem;  // [128 co][132] = 67584 B
#pragma unroll
    for (int mi = 0; mi < 2; mi++)
#pragma unroll
        for (int ni = 0; ni < 8; ni++) {
            int m = warp_m * 32 + mi * 16 + (lane >> 2);
            int n = warp_n * 64 + ni * 8 + 2 * (lane & 3);
            const float* a = d[mi][ni];
            red[n * 132 + m] = a[0];
            red[(n + 1) * 132 + m] = a[1];
            red[n * 132 + m + 8] = a[2];
            red[(n + 1) * 132 + m + 8] = a[3];
        }
    __syncthreads();
    {
        int col = tid >> 1, half = tid & 1;       // col 0..127 local
        int co = nhalf * 128 + col;
        float c = g_ca[b * CO_ + co];
        const float4* rp = (const float4*)(red + col * 132 + half * 64);
        float* op = out + ((size_t)(b * CO_ + co)) * HW_ + tile * 128 + half * 64;
#pragma unroll
        for (int i = 0; i < 16; i++) {
            float4 v = rp[i];
            v.x *= c; v.y *= c; v.z *= c; v.w *= c;
            ((float4*)op)[i] = v;
        }
    }
}

// ---------------- launch ----------------
extern "C" void kernel_launch(void* const* d_in, const int* in_sizes, int n_in,
                              void* d_out, int out_size) {
    const float* x       = (const float*)d_in[0];
    const float* experts = (const float*)d_in[1];
    const float* rw1 = (const float*)d_in[2];
    const float* rb1 = (const float*)d_in[3];
    const float* rw2 = (const float*)d_in[4];
    const float* rb2 = (const float*)d_in[5];
    const float* rw3 = (const float*)d_in[6];
    const float* rb3 = (const float*)d_in[7];
    const float* aw1 = (const float*)d_in[8];
    const float* ab1 = (const float*)d_in[9];
    const float* aw2 = (const float*)d_in[10];
    const float* ab2 = (const float*)d_in[11];
    float* out = (float*)d_out;

    cudaFuncSetAttribute(conv_mma_kernel, cudaFuncAttributeMaxDynamicSharedMemorySize,
                         SMEM_TOTAL);

    xprep_kernel<<<B_ * CI_, 256>>>(x);
    routing_kernel<<<B_, 128>>>(rw1, rb1, rw2, rb2, rw3, rb3);
    combine_kernel<<<dim3(CO_, 4), 128>>>(experts);
    attn_kernel<<<B_, 256>>>(aw1, ab1, aw2, ab2);
    conv_mma_kernel<<<dim3(32, 2, B_), 256, SMEM_TOTAL>>>(out);
}